// round 3
// baseline (speedup 1.0000x reference)
#include <cuda_runtime.h>
#include <math_constants.h>
#include <stdint.h>

// Problem constants
#define N_ROWS 4096
#define DIM    144
#define KCODES 50257
#define MROWS  128                       // rows per block tile
#define CT     64                        // codes per smem tile
#define NTILES ((KCODES + CT - 1) / CT)  // 786
#define NCHUNK 19
#define TPC    ((NTILES + NCHUNK - 1) / NCHUNK) // 42 tiles per chunk
#define ZQ_ELEMS (N_ROWS * DIM)          // 589824
#define SMEM_BYTES ((DIM * MROWS + DIM * CT + CT) * 4) // 110848

// Scratch (no allocations allowed -> device globals)
__device__ float  g_zn[N_ROWS];
__device__ float  g_en[KCODES];
__device__ float  g_pval[NCHUNK * N_ROWS];
__device__ int    g_pidx[NCHUNK * N_ROWS];
__device__ double g_loss;

// ---------------------------------------------------------------------------
// Kernel 1: row norms of z (NEON-style 4-lane order to mimic XLA CPU reduce),
//           code norms of emb (order-insensitive), zero loss accumulator.
// ---------------------------------------------------------------------------
__global__ void prep_kernel(const float* __restrict__ z,
                            const float* __restrict__ emb)
{
    int gid = blockIdx.x * blockDim.x + threadIdx.x;
    if (gid == 0) g_loss = 0.0;

    if (gid < N_ROWS) {
        const float4* p = reinterpret_cast<const float4*>(z + (size_t)gid * DIM);
        float p0 = 0.f, p1 = 0.f, p2 = 0.f, p3 = 0.f;
        #pragma unroll
        for (int i = 0; i < DIM / 4; ++i) {
            float4 v = p[i];
            p0 = __fmaf_rn(v.x, v.x, p0);
            p1 = __fmaf_rn(v.y, v.y, p1);
            p2 = __fmaf_rn(v.z, v.z, p2);
            p3 = __fmaf_rn(v.w, v.w, p3);
        }
        // faddp-style horizontal: (p0+p1) + (p2+p3)
        g_zn[gid] = __fadd_rn(__fadd_rn(p0, p1), __fadd_rn(p2, p3));
    }

    if (gid < KCODES) {
        const float4* p = reinterpret_cast<const float4*>(emb + (size_t)gid * DIM);
        float p0 = 0.f, p1 = 0.f, p2 = 0.f, p3 = 0.f;
        #pragma unroll
        for (int i = 0; i < DIM / 4; ++i) {
            float4 v = p[i];
            p0 = __fmaf_rn(v.x, v.x, p0);
            p1 = __fmaf_rn(v.y, v.y, p1);
            p2 = __fmaf_rn(v.z, v.z, p2);
            p3 = __fmaf_rn(v.w, v.w, p3);
        }
        g_en[gid] = __fadd_rn(__fadd_rn(p0, p1), __fadd_rn(p2, p3));
    }
}

// ---------------------------------------------------------------------------
// Kernel 2: tiled distance + running argmin.
// Block tile: 128 rows x (TPC*64) codes. 256 threads = 16(tx: codes) x 16(ty: rows).
// Each thread: 8 rows x 4 codes accumulators, dot over d ascending (matches
// sequential fp32 dot to ~1e-10 which is far below the 1.5e-5 quantization).
// ---------------------------------------------------------------------------
__global__ void __launch_bounds__(256, 2)
dist_kernel(const float* __restrict__ z, const float* __restrict__ emb)
{
    extern __shared__ float smem[];
    float* z_s  = smem;                     // [DIM][MROWS]
    float* e_s  = smem + DIM * MROWS;       // [DIM][CT], XOR-4 swizzled in code dim
    float* en_s = e_s  + DIM * CT;          // [CT]

    const int tid = threadIdx.x;
    const int tx = tid & 15;
    const int ty = tid >> 4;
    const int rowbase = blockIdx.x * MROWS;
    const int chunk = blockIdx.y;
    const int t0 = chunk * TPC;
    const int t1 = min(t0 + TPC, NTILES);

    // Load z tile transposed into smem (one-time; STS conflicts tolerated).
    for (int k4 = tid; k4 < MROWS * DIM / 4; k4 += 256) {
        int k = k4 << 2;
        int r = k / DIM;
        int d0 = k - r * DIM;
        float4 v = *reinterpret_cast<const float4*>(z + (size_t)(rowbase + r) * DIM + d0);
        z_s[(d0 + 0) * MROWS + r] = v.x;
        z_s[(d0 + 1) * MROWS + r] = v.y;
        z_s[(d0 + 2) * MROWS + r] = v.z;
        z_s[(d0 + 3) * MROWS + r] = v.w;
    }

    float zn_reg[8];
    #pragma unroll
    for (int i = 0; i < 8; ++i)
        zn_reg[i] = g_zn[rowbase + ty * 8 + i];

    float bestv[8];
    int   besti[8];
    #pragma unroll
    for (int i = 0; i < 8; ++i) { bestv[i] = CUDART_INF_F; besti[i] = 0x7fffffff; }

    for (int t = t0; t < t1; ++t) {
        const int cbase = t * CT;

        // Load emb tile transposed + swizzled: e_s[d*CT + (c ^ ((d&15)<<2))]
        for (int k4 = tid; k4 < CT * DIM / 4; k4 += 256) {
            int k = k4 << 2;
            int c = k / DIM;
            int d0 = k - c * DIM;
            int cg = cbase + c;
            float4 v = make_float4(0.f, 0.f, 0.f, 0.f);
            if (cg < KCODES)
                v = *reinterpret_cast<const float4*>(emb + (size_t)cg * DIM + d0);
            e_s[(d0 + 0) * CT + (c ^ (((d0 + 0) & 15) << 2))] = v.x;
            e_s[(d0 + 1) * CT + (c ^ (((d0 + 1) & 15) << 2))] = v.y;
            e_s[(d0 + 2) * CT + (c ^ (((d0 + 2) & 15) << 2))] = v.z;
            e_s[(d0 + 3) * CT + (c ^ (((d0 + 3) & 15) << 2))] = v.w;
        }
        if (tid < CT) {
            int cg = cbase + tid;
            en_s[tid] = (cg < KCODES) ? g_en[cg] : CUDART_INF_F;
        }
        __syncthreads();

        float acc[32];
        #pragma unroll
        for (int u = 0; u < 32; ++u) acc[u] = 0.f;

        #pragma unroll 4
        for (int d = 0; d < DIM; ++d) {
            const float4 za = *reinterpret_cast<const float4*>(z_s + d * MROWS + (ty << 3));
            const float4 zb = *reinterpret_cast<const float4*>(z_s + d * MROWS + (ty << 3) + 4);
            const float4 ev = *reinterpret_cast<const float4*>(
                e_s + d * CT + (((tx << 2)) ^ ((d & 15) << 2)));
            float zr[8] = {za.x, za.y, za.z, za.w, zb.x, zb.y, zb.z, zb.w};
            float er[4] = {ev.x, ev.y, ev.z, ev.w};
            #pragma unroll
            for (int i = 0; i < 8; ++i)
                #pragma unroll
                for (int j = 0; j < 4; ++j)
                    acc[i * 4 + j] = __fmaf_rn(zr[i], er[j], acc[i * 4 + j]);
        }

        // Epilogue: score = fl(fl(zn+en) - 2*dot); strict < keeps first index.
        #pragma unroll
        for (int j = 0; j < 4; ++j) {
            const int cg = cbase + (tx << 2) + j;
            const float en = en_s[(tx << 2) + j];
            #pragma unroll
            for (int i = 0; i < 8; ++i) {
                float t1v = __fadd_rn(zn_reg[i], en);
                float dd = __fmaf_rn(acc[i * 4 + j], -2.0f, t1v);
                if (dd < bestv[i]) { bestv[i] = dd; besti[i] = cg; }
            }
        }
        __syncthreads();
    }

    // Reduce over the 16 tx lanes sharing each row (xor stays within 16-half).
    #pragma unroll
    for (int i = 0; i < 8; ++i) {
        float v = bestv[i];
        int   b = besti[i];
        #pragma unroll
        for (int m = 8; m > 0; m >>= 1) {
            float v2 = __shfl_xor_sync(0xffffffffu, v, m);
            int   b2 = __shfl_xor_sync(0xffffffffu, b, m);
            if (v2 < v || (v2 == v && b2 < b)) { v = v2; b = b2; }
        }
        if (tx == 0) {
            int r = rowbase + ty * 8 + i;
            g_pval[chunk * N_ROWS + r] = v;
            g_pidx[chunk * N_ROWS + r] = b;
        }
    }
}

// ---------------------------------------------------------------------------
// Kernel 3: per-row cross-chunk argmin, gather z_q, accumulate loss.
// ---------------------------------------------------------------------------
__global__ void finalize_kernel(const float* __restrict__ z,
                                const float* __restrict__ emb,
                                float* __restrict__ out)
{
    int r = blockIdx.x * 256 + threadIdx.x;
    double lsum = 0.0;
    if (r < N_ROWS) {
        float bv = CUDART_INF_F;
        int   bi = 0x7fffffff;
        #pragma unroll
        for (int c = 0; c < NCHUNK; ++c) {
            float v = g_pval[c * N_ROWS + r];
            int   b = g_pidx[c * N_ROWS + r];
            if (v < bv || (v == bv && b < bi)) { bv = v; bi = b; }
        }
        out[ZQ_ELEMS + r] = (float)bi;

        const float4* ep = reinterpret_cast<const float4*>(emb + (size_t)bi * DIM);
        const float4* zp = reinterpret_cast<const float4*>(z + (size_t)r * DIM);
        float4* op = reinterpret_cast<float4*>(out + (size_t)r * DIM);
        #pragma unroll 4
        for (int i = 0; i < DIM / 4; ++i) {
            float4 e = ep[i];
            float4 zz = zp[i];
            op[i] = e;
            float dx = e.x - zz.x, dy = e.y - zz.y, dz = e.z - zz.z, dw = e.w - zz.w;
            lsum += (double)dx * dx + (double)dy * dy + (double)dz * dz + (double)dw * dw;
        }
    }
    __shared__ double red[256];
    red[threadIdx.x] = lsum;
    __syncthreads();
    for (int s = 128; s > 0; s >>= 1) {
        if (threadIdx.x < s) red[threadIdx.x] += red[threadIdx.x + s];
        __syncthreads();
    }
    if (threadIdx.x == 0) atomicAdd(&g_loss, red[0]);
}

// Kernel 4: write scalar loss.
__global__ void loss_kernel(float* __restrict__ out)
{
    out[ZQ_ELEMS + N_ROWS] = (float)(g_loss / (double)ZQ_ELEMS);
}

// ---------------------------------------------------------------------------
extern "C" void kernel_launch(void* const* d_in, const int* in_sizes, int n_in,
                              void* d_out, int out_size)
{
    const float* z = nullptr;
    const float* emb = nullptr;
    for (int i = 0; i < n_in; ++i) {
        if (in_sizes[i] == N_ROWS * DIM)      z = (const float*)d_in[i];
        else if (in_sizes[i] == KCODES * DIM) emb = (const float*)d_in[i];
    }
    float* out = (float*)d_out;
    (void)out_size;

    cudaFuncSetAttribute(dist_kernel,
                         cudaFuncAttributeMaxDynamicSharedMemorySize, SMEM_BYTES);

    prep_kernel<<<(KCODES + 255) / 256, 256>>>(z, emb);
    dist_kernel<<<dim3(N_ROWS / MROWS, NCHUNK), 256, SMEM_BYTES>>>(z, emb);
    finalize_kernel<<<N_ROWS / 256, 256>>>(z, emb, out);
    loss_kernel<<<1, 1>>>(out);
}

// round 4
// speedup vs baseline: 2.7754x; 2.7754x over previous
#include <cuda_runtime.h>
#include <cuda_bf16.h>
#include <math_constants.h>
#include <stdint.h>

#define N_ROWS 4096
#define DIM    144
#define KCODES 50257
#define KPADC  50304                 // 393 * 128
#define KP     152                   // padded bf16 row width (304 bytes)
#define NT128  393
#define NT64   786
#define NCHUNK 19
#define TPC    21                    // ceil(393/19)
#define ZQ_ELEMS (N_ROWS * DIM)
#define MARGIN 1e-4f
#define GEMM_SMEM (38912*2 + 512 + 2048)   // As + Bs + ens + red = 80384

// ---- scratch (device globals; no allocations allowed) ----
__device__ float          g_zn[N_ROWS];
__device__ float          g_en[KPADC];
__device__ __nv_bfloat16  g_zb[(size_t)N_ROWS * KP];
__device__ __nv_bfloat16  g_eb[(size_t)KPADC * KP];
__device__ float          g_tmin[(size_t)NT64 * N_ROWS];   // [tile64][row]
__device__ double         g_rowloss[N_ROWS];

// ---------------------------------------------------------------------------
// Kernel 1: exact norms (NEON 4-lane order, proven bit-matching in R2) and
//           bf16 copies of z and emb (row width padded to 152).
// ---------------------------------------------------------------------------
__global__ void prep_kernel(const float* __restrict__ z,
                            const float* __restrict__ emb)
{
    int gid = blockIdx.x * blockDim.x + threadIdx.x;
    __nv_bfloat162 zero2 = __float22bfloat162_rn(make_float2(0.f, 0.f));

    if (gid < N_ROWS) {
        const float4* p = reinterpret_cast<const float4*>(z + (size_t)gid * DIM);
        __nv_bfloat162* dst = reinterpret_cast<__nv_bfloat162*>(g_zb + (size_t)gid * KP);
        float p0 = 0.f, p1 = 0.f, p2 = 0.f, p3 = 0.f;
        #pragma unroll
        for (int i = 0; i < DIM / 4; ++i) {
            float4 v = p[i];
            p0 = __fmaf_rn(v.x, v.x, p0);
            p1 = __fmaf_rn(v.y, v.y, p1);
            p2 = __fmaf_rn(v.z, v.z, p2);
            p3 = __fmaf_rn(v.w, v.w, p3);
            dst[i * 2 + 0] = __float22bfloat162_rn(make_float2(v.x, v.y));
            dst[i * 2 + 1] = __float22bfloat162_rn(make_float2(v.z, v.w));
        }
        #pragma unroll
        for (int i = 72; i < KP / 2; ++i) dst[i] = zero2;
        g_zn[gid] = __fadd_rn(__fadd_rn(p0, p1), __fadd_rn(p2, p3));
    }

    if (gid < KPADC) {
        __nv_bfloat162* dst = reinterpret_cast<__nv_bfloat162*>(g_eb + (size_t)gid * KP);
        if (gid < KCODES) {
            const float4* p = reinterpret_cast<const float4*>(emb + (size_t)gid * DIM);
            float p0 = 0.f, p1 = 0.f, p2 = 0.f, p3 = 0.f;
            #pragma unroll
            for (int i = 0; i < DIM / 4; ++i) {
                float4 v = p[i];
                p0 = __fmaf_rn(v.x, v.x, p0);
                p1 = __fmaf_rn(v.y, v.y, p1);
                p2 = __fmaf_rn(v.z, v.z, p2);
                p3 = __fmaf_rn(v.w, v.w, p3);
                dst[i * 2 + 0] = __float22bfloat162_rn(make_float2(v.x, v.y));
                dst[i * 2 + 1] = __float22bfloat162_rn(make_float2(v.z, v.w));
            }
            #pragma unroll
            for (int i = 72; i < KP / 2; ++i) dst[i] = zero2;
            g_en[gid] = __fadd_rn(__fadd_rn(p0, p1), __fadd_rn(p2, p3));
        } else {
            for (int i = 0; i < KP / 2; ++i) dst[i] = zero2;
            g_en[gid] = CUDART_INF_F;
        }
    }
}

// ---------------------------------------------------------------------------
// Kernel 2: bf16 mma.sync GEMM producing per-(row, 64-code-tile) approx min d.
// Block tile 128 rows x 128 codes, 8 warps as 2(M) x 4(N), warp tile 64x32.
// ---------------------------------------------------------------------------
__device__ __forceinline__ void mma16816(float* c, const uint32_t* a, const uint32_t* b)
{
    asm volatile(
        "mma.sync.aligned.m16n8k16.row.col.f32.bf16.bf16.f32 "
        "{%0,%1,%2,%3}, {%4,%5,%6,%7}, {%8,%9}, {%0,%1,%2,%3};\n"
        : "+f"(c[0]), "+f"(c[1]), "+f"(c[2]), "+f"(c[3])
        : "r"(a[0]), "r"(a[1]), "r"(a[2]), "r"(a[3]), "r"(b[0]), "r"(b[1]));
}

__global__ void __launch_bounds__(256, 2) gemm_kernel()
{
    extern __shared__ char smem[];
    __nv_bfloat16* As = reinterpret_cast<__nv_bfloat16*>(smem);            // [128][152]
    __nv_bfloat16* Bs = reinterpret_cast<__nv_bfloat16*>(smem + 38912);    // [128][152]
    float* ens = reinterpret_cast<float*>(smem + 77824);                   // [128]
    float* red = reinterpret_cast<float*>(smem + 78336);                   // [4][128]

    const int tid  = threadIdx.x;
    const int lane = tid & 31;
    const int wid  = tid >> 5;
    const int wm   = wid >> 2;        // 0..1  (row warp)
    const int wn   = wid & 3;         // 0..3  (col warp)
    const int g    = lane >> 2;       // group id 0..7
    const int q    = lane & 3;        // thread-in-group
    const int rowbase = blockIdx.x * 128;

    // Load A tile (rows are contiguous in g_zb)
    {
        const uint4* src = reinterpret_cast<const uint4*>(g_zb + (size_t)rowbase * KP);
        uint4* dst = reinterpret_cast<uint4*>(As);
        #pragma unroll 4
        for (int i = tid; i < 128 * 19; i += 256) dst[i] = src[i];
    }

    float zr[4][2];
    #pragma unroll
    for (int mi = 0; mi < 4; ++mi)
        #pragma unroll
        for (int rh = 0; rh < 2; ++rh)
            zr[mi][rh] = g_zn[rowbase + wm * 64 + mi * 16 + rh * 8 + g];

    const char* aB = reinterpret_cast<const char*>(As) + (wm * 64 + g) * 304 + q * 4;
    const char* bB = reinterpret_cast<const char*>(Bs) + (wn * 32 + g) * 304 + q * 4;

    for (int jj = 0; jj < TPC; ++jj) {
        int j = blockIdx.y * TPC + jj;
        if (j >= NT128) break;
        const int cbase = j * 128;

        // Load B tile + en slice
        {
            const uint4* src = reinterpret_cast<const uint4*>(g_eb + (size_t)cbase * KP);
            uint4* dst = reinterpret_cast<uint4*>(Bs);
            #pragma unroll 4
            for (int i = tid; i < 128 * 19; i += 256) dst[i] = src[i];
            if (tid < 128) ens[tid] = g_en[cbase + tid];
        }
        __syncthreads();

        float c[4][4][4];
        #pragma unroll
        for (int mi = 0; mi < 4; ++mi)
            #pragma unroll
            for (int ni = 0; ni < 4; ++ni)
                #pragma unroll
                for (int k = 0; k < 4; ++k) c[mi][ni][k] = 0.f;

        #pragma unroll
        for (int ks = 0; ks < 9; ++ks) {
            const int ko = ks * 32;    // kk*2 bytes (kk = 16*ks bf16)
            uint32_t a[4][4], b[4][2];
            #pragma unroll
            for (int mi = 0; mi < 4; ++mi) {
                a[mi][0] = *reinterpret_cast<const uint32_t*>(aB + mi * 4864 + ko);
                a[mi][1] = *reinterpret_cast<const uint32_t*>(aB + mi * 4864 + 2432 + ko);
                a[mi][2] = *reinterpret_cast<const uint32_t*>(aB + mi * 4864 + ko + 16);
                a[mi][3] = *reinterpret_cast<const uint32_t*>(aB + mi * 4864 + 2432 + ko + 16);
            }
            #pragma unroll
            for (int ni = 0; ni < 4; ++ni) {
                b[ni][0] = *reinterpret_cast<const uint32_t*>(bB + ni * 2432 + ko);
                b[ni][1] = *reinterpret_cast<const uint32_t*>(bB + ni * 2432 + ko + 16);
            }
            #pragma unroll
            for (int mi = 0; mi < 4; ++mi)
                #pragma unroll
                for (int ni = 0; ni < 4; ++ni)
                    mma16816(c[mi][ni], a[mi], b[ni]);
        }

        // Epilogue: approx d = fma(dot, -2, zn + en); per-row min over this tile.
        float ev[4][2];
        #pragma unroll
        for (int ni = 0; ni < 4; ++ni) {
            ev[ni][0] = ens[wn * 32 + ni * 8 + q * 2 + 0];
            ev[ni][1] = ens[wn * 32 + ni * 8 + q * 2 + 1];
        }
        #pragma unroll
        for (int mi = 0; mi < 4; ++mi) {
            #pragma unroll
            for (int rh = 0; rh < 2; ++rh) {
                float v = CUDART_INF_F;
                #pragma unroll
                for (int ni = 0; ni < 4; ++ni) {
                    v = fminf(v, __fmaf_rn(c[mi][ni][rh * 2 + 0], -2.f, zr[mi][rh] + ev[ni][0]));
                    v = fminf(v, __fmaf_rn(c[mi][ni][rh * 2 + 1], -2.f, zr[mi][rh] + ev[ni][1]));
                }
                v = fminf(v, __shfl_xor_sync(0xffffffffu, v, 1));
                v = fminf(v, __shfl_xor_sync(0xffffffffu, v, 2));
                if (q == 0)
                    red[wn * 128 + wm * 64 + mi * 16 + rh * 8 + g] = v;
            }
        }
        __syncthreads();
        if (tid < 128) {
            float h0 = fminf(red[tid],       red[128 + tid]);   // codes 0..63
            float h1 = fminf(red[256 + tid], red[384 + tid]);   // codes 64..127
            g_tmin[(size_t)(j * 2 + 0) * N_ROWS + rowbase + tid] = h0;
            g_tmin[(size_t)(j * 2 + 1) * N_ROWS + rowbase + tid] = h1;
        }
        __syncthreads();
    }
}

// ---------------------------------------------------------------------------
// Kernel 3: per-row exact rescore of candidate tiles; emits index, z_q, loss.
// ---------------------------------------------------------------------------
__global__ void __launch_bounds__(128) rescore_kernel(const float* __restrict__ z,
                                                      const float* __restrict__ emb,
                                                      float* __restrict__ out)
{
    __shared__ float  zs[DIM];
    __shared__ float  smin[128];
    __shared__ int    list[NT64];
    __shared__ int    cnt;
    __shared__ float  stage[64 * 145];    // padded stride 145: bank-safe
    __shared__ float  rbv[128];
    __shared__ int    rbi[128];
    __shared__ double dred[128];

    const int row = blockIdx.x;
    const int tid = threadIdx.x;

    // pass over tile mins: cache locally, find global min
    float tv[7]; int ti[7]; int nl = 0;
    float m = CUDART_INF_F;
    for (int i = tid; i < NT64; i += 128) {
        float v = g_tmin[(size_t)i * N_ROWS + row];
        tv[nl] = v; ti[nl] = i; ++nl;
        m = fminf(m, v);
    }
    for (int i = tid; i < DIM; i += 128) zs[i] = z[(size_t)row * DIM + i];
    if (tid == 0) cnt = 0;
    smin[tid] = m;
    __syncthreads();
    for (int s = 64; s > 0; s >>= 1) {
        if (tid < s) smin[tid] = fminf(smin[tid], smin[tid + s]);
        __syncthreads();
    }
    const float tau = smin[0] + MARGIN;
    for (int u = 0; u < nl; ++u)
        if (tv[u] <= tau) list[atomicAdd(&cnt, 1)] = ti[u];
    __syncthreads();
    const int nc = cnt;
    const float zn = g_zn[row];

    float bv = CUDART_INF_F;
    int   bi = 0x7fffffff;
    for (int li = 0; li < nc; ++li) {
        const int t64 = list[li];
        const int cb = t64 * 64;
        for (int idx = tid; idx < 64 * DIM; idx += 128) {
            int r = idx / DIM;
            int col = idx - r * DIM;
            int code = cb + r;
            stage[r * 145 + col] = (code < KCODES) ? emb[(size_t)code * DIM + col] : 0.f;
        }
        __syncthreads();
        if (tid < 64) {
            int code = cb + tid;
            if (code < KCODES) {
                float acc = 0.f;
                const float* es = &stage[tid * 145];
                #pragma unroll 8
                for (int d = 0; d < DIM; ++d)
                    acc = __fmaf_rn(zs[d], es[d], acc);
                float t1 = __fadd_rn(zn, g_en[code]);
                float dd = __fmaf_rn(acc, -2.f, t1);
                if (dd < bv || (dd == bv && code < bi)) { bv = dd; bi = code; }
            }
        }
        __syncthreads();
    }

    rbv[tid] = bv; rbi[tid] = bi;
    __syncthreads();
    for (int s = 64; s > 0; s >>= 1) {
        if (tid < s) {
            float v2 = rbv[tid + s]; int b2 = rbi[tid + s];
            if (v2 < rbv[tid] || (v2 == rbv[tid] && b2 < rbi[tid])) {
                rbv[tid] = v2; rbi[tid] = b2;
            }
        }
        __syncthreads();
    }
    const int wbi = rbi[0];
    if (tid == 0) out[ZQ_ELEMS + row] = (float)wbi;

    double ls = 0.0;
    for (int i = tid; i < DIM; i += 128) {
        float e = emb[(size_t)wbi * DIM + i];
        out[(size_t)row * DIM + i] = e;
        float dx = e - zs[i];
        ls += (double)dx * dx;
    }
    dred[tid] = ls;
    __syncthreads();
    for (int s = 64; s > 0; s >>= 1) {
        if (tid < s) dred[tid] += dred[tid + s];
        __syncthreads();
    }
    if (tid == 0) g_rowloss[row] = dred[0];
}

// Kernel 4: deterministic loss reduction.
__global__ void loss_kernel(float* __restrict__ out)
{
    __shared__ double dred[256];
    int tid = threadIdx.x;
    double s = 0.0;
    for (int i = tid; i < N_ROWS; i += 256) s += g_rowloss[i];
    dred[tid] = s;
    __syncthreads();
    for (int st = 128; st > 0; st >>= 1) {
        if (tid < st) dred[tid] += dred[tid + st];
        __syncthreads();
    }
    if (tid == 0) out[ZQ_ELEMS + N_ROWS] = (float)(dred[0] / (double)ZQ_ELEMS);
}

// ---------------------------------------------------------------------------
extern "C" void kernel_launch(void* const* d_in, const int* in_sizes, int n_in,
                              void* d_out, int out_size)
{
    const float* z = nullptr;
    const float* emb = nullptr;
    for (int i = 0; i < n_in; ++i) {
        if (in_sizes[i] == N_ROWS * DIM)      z = (const float*)d_in[i];
        else if (in_sizes[i] == KCODES * DIM) emb = (const float*)d_in[i];
    }
    float* out = (float*)d_out;
    (void)out_size;

    cudaFuncSetAttribute(gemm_kernel,
                         cudaFuncAttributeMaxDynamicSharedMemorySize, GEMM_SMEM);

    prep_kernel<<<(KPADC + 255) / 256, 256>>>(z, emb);
    gemm_kernel<<<dim3(N_ROWS / 128, NCHUNK), 256, GEMM_SMEM>>>();
    rescore_kernel<<<N_ROWS, 128>>>(z, emb, out);
    loss_kernel<<<1, 256>>>(out);
}

// round 5
// speedup vs baseline: 2.7847x; 1.0033x over previous
#include <cuda_runtime.h>
#include <cuda_bf16.h>
#include <math_constants.h>
#include <stdint.h>

#define N_ROWS 4096
#define DIM    144
#define KCODES 50257
#define KPADC  50304                 // 393 * 128
#define KP     152                   // padded bf16 row width (304 bytes)
#define NT128  393
#define NT64   786
#define NCHUNK 19
#define TPC    21                    // ceil(393/19)
#define ZQ_ELEMS (N_ROWS * DIM)
#define MARGIN 1e-4f
#define GEMM_SMEM (38912*2 + 512 + 2048)   // As + Bs + ens + red = 80384

// ---- scratch (device globals; no allocations allowed) ----
__device__ float          g_zn[N_ROWS];
__device__ float          g_en[KPADC];
__device__ __nv_bfloat16  g_zb[(size_t)N_ROWS * KP];
__device__ __nv_bfloat16  g_eb[(size_t)KPADC * KP];
__device__ float          g_tmin[(size_t)NT64 * N_ROWS];   // [tile64][row]
__device__ double         g_rowloss[N_ROWS];

// ---------------------------------------------------------------------------
// Kernel 1: exact norms (NEON 4-lane order, proven bit-matching in R2) and
//           bf16 copies of z and emb (row width padded to 152).
// ---------------------------------------------------------------------------
__global__ void prep_kernel(const float* __restrict__ z,
                            const float* __restrict__ emb)
{
    int gid = blockIdx.x * blockDim.x + threadIdx.x;
    __nv_bfloat162 zero2 = __float22bfloat162_rn(make_float2(0.f, 0.f));

    if (gid < N_ROWS) {
        const float4* p = reinterpret_cast<const float4*>(z + (size_t)gid * DIM);
        __nv_bfloat162* dst = reinterpret_cast<__nv_bfloat162*>(g_zb + (size_t)gid * KP);
        float p0 = 0.f, p1 = 0.f, p2 = 0.f, p3 = 0.f;
        #pragma unroll
        for (int i = 0; i < DIM / 4; ++i) {
            float4 v = p[i];
            p0 = __fmaf_rn(v.x, v.x, p0);
            p1 = __fmaf_rn(v.y, v.y, p1);
            p2 = __fmaf_rn(v.z, v.z, p2);
            p3 = __fmaf_rn(v.w, v.w, p3);
            dst[i * 2 + 0] = __float22bfloat162_rn(make_float2(v.x, v.y));
            dst[i * 2 + 1] = __float22bfloat162_rn(make_float2(v.z, v.w));
        }
        #pragma unroll
        for (int i = 72; i < KP / 2; ++i) dst[i] = zero2;
        g_zn[gid] = __fadd_rn(__fadd_rn(p0, p1), __fadd_rn(p2, p3));
    }

    if (gid < KPADC) {
        __nv_bfloat162* dst = reinterpret_cast<__nv_bfloat162*>(g_eb + (size_t)gid * KP);
        if (gid < KCODES) {
            const float4* p = reinterpret_cast<const float4*>(emb + (size_t)gid * DIM);
            float p0 = 0.f, p1 = 0.f, p2 = 0.f, p3 = 0.f;
            #pragma unroll
            for (int i = 0; i < DIM / 4; ++i) {
                float4 v = p[i];
                p0 = __fmaf_rn(v.x, v.x, p0);
                p1 = __fmaf_rn(v.y, v.y, p1);
                p2 = __fmaf_rn(v.z, v.z, p2);
                p3 = __fmaf_rn(v.w, v.w, p3);
                dst[i * 2 + 0] = __float22bfloat162_rn(make_float2(v.x, v.y));
                dst[i * 2 + 1] = __float22bfloat162_rn(make_float2(v.z, v.w));
            }
            #pragma unroll
            for (int i = 72; i < KP / 2; ++i) dst[i] = zero2;
            g_en[gid] = __fadd_rn(__fadd_rn(p0, p1), __fadd_rn(p2, p3));
        } else {
            for (int i = 0; i < KP / 2; ++i) dst[i] = zero2;
            g_en[gid] = CUDART_INF_F;
        }
    }
}

// ---------------------------------------------------------------------------
// Kernel 2: bf16 mma.sync GEMM producing per-(row, 64-code-tile) approx min d.
// Block tile 128 rows x 128 codes, 8 warps as 2(M) x 4(N), warp tile 64x32.
// ---------------------------------------------------------------------------
__device__ __forceinline__ void mma16816(float* c, const uint32_t* a, const uint32_t* b)
{
    asm volatile(
        "mma.sync.aligned.m16n8k16.row.col.f32.bf16.bf16.f32 "
        "{%0,%1,%2,%3}, {%4,%5,%6,%7}, {%8,%9}, {%0,%1,%2,%3};\n"
        : "+f"(c[0]), "+f"(c[1]), "+f"(c[2]), "+f"(c[3])
        : "r"(a[0]), "r"(a[1]), "r"(a[2]), "r"(a[3]), "r"(b[0]), "r"(b[1]));
}

__global__ void __launch_bounds__(256, 2) gemm_kernel()
{
    extern __shared__ char smem[];
    __nv_bfloat16* As = reinterpret_cast<__nv_bfloat16*>(smem);            // [128][152]
    __nv_bfloat16* Bs = reinterpret_cast<__nv_bfloat16*>(smem + 38912);    // [128][152]
    float* ens = reinterpret_cast<float*>(smem + 77824);                   // [128]
    float* red = reinterpret_cast<float*>(smem + 78336);                   // [4][128]

    const int tid  = threadIdx.x;
    const int lane = tid & 31;
    const int wid  = tid >> 5;
    const int wm   = wid >> 2;        // 0..1  (row warp)
    const int wn   = wid & 3;         // 0..3  (col warp)
    const int g    = lane >> 2;       // group id 0..7
    const int q    = lane & 3;        // thread-in-group
    const int rowbase = blockIdx.x * 128;

    // Load A tile (rows are contiguous in g_zb)
    {
        const uint4* src = reinterpret_cast<const uint4*>(g_zb + (size_t)rowbase * KP);
        uint4* dst = reinterpret_cast<uint4*>(As);
        #pragma unroll 4
        for (int i = tid; i < 128 * 19; i += 256) dst[i] = src[i];
    }

    float zr[4][2];
    #pragma unroll
    for (int mi = 0; mi < 4; ++mi)
        #pragma unroll
        for (int rh = 0; rh < 2; ++rh)
            zr[mi][rh] = g_zn[rowbase + wm * 64 + mi * 16 + rh * 8 + g];

    const char* aB = reinterpret_cast<const char*>(As) + (wm * 64 + g) * 304 + q * 4;
    const char* bB = reinterpret_cast<const char*>(Bs) + (wn * 32 + g) * 304 + q * 4;

    for (int jj = 0; jj < TPC; ++jj) {
        int j = blockIdx.y * TPC + jj;
        if (j >= NT128) break;
        const int cbase = j * 128;

        // Load B tile + en slice
        {
            const uint4* src = reinterpret_cast<const uint4*>(g_eb + (size_t)cbase * KP);
            uint4* dst = reinterpret_cast<uint4*>(Bs);
            #pragma unroll 4
            for (int i = tid; i < 128 * 19; i += 256) dst[i] = src[i];
            if (tid < 128) ens[tid] = g_en[cbase + tid];
        }
        __syncthreads();

        float c[4][4][4];
        #pragma unroll
        for (int mi = 0; mi < 4; ++mi)
            #pragma unroll
            for (int ni = 0; ni < 4; ++ni)
                #pragma unroll
                for (int k = 0; k < 4; ++k) c[mi][ni][k] = 0.f;

        #pragma unroll
        for (int ks = 0; ks < 9; ++ks) {
            const int ko = ks * 32;    // kk*2 bytes (kk = 16*ks bf16)
            uint32_t a[4][4], b[4][2];
            #pragma unroll
            for (int mi = 0; mi < 4; ++mi) {
                a[mi][0] = *reinterpret_cast<const uint32_t*>(aB + mi * 4864 + ko);
                a[mi][1] = *reinterpret_cast<const uint32_t*>(aB + mi * 4864 + 2432 + ko);
                a[mi][2] = *reinterpret_cast<const uint32_t*>(aB + mi * 4864 + ko + 16);
                a[mi][3] = *reinterpret_cast<const uint32_t*>(aB + mi * 4864 + 2432 + ko + 16);
            }
            #pragma unroll
            for (int ni = 0; ni < 4; ++ni) {
                b[ni][0] = *reinterpret_cast<const uint32_t*>(bB + ni * 2432 + ko);
                b[ni][1] = *reinterpret_cast<const uint32_t*>(bB + ni * 2432 + ko + 16);
            }
            #pragma unroll
            for (int mi = 0; mi < 4; ++mi)
                #pragma unroll
                for (int ni = 0; ni < 4; ++ni)
                    mma16816(c[mi][ni], a[mi], b[ni]);
        }

        // Epilogue: approx d = fma(dot, -2, zn + en); per-row min over this tile.
        float ev[4][2];
        #pragma unroll
        for (int ni = 0; ni < 4; ++ni) {
            ev[ni][0] = ens[wn * 32 + ni * 8 + q * 2 + 0];
            ev[ni][1] = ens[wn * 32 + ni * 8 + q * 2 + 1];
        }
        #pragma unroll
        for (int mi = 0; mi < 4; ++mi) {
            #pragma unroll
            for (int rh = 0; rh < 2; ++rh) {
                float v = CUDART_INF_F;
                #pragma unroll
                for (int ni = 0; ni < 4; ++ni) {
                    v = fminf(v, __fmaf_rn(c[mi][ni][rh * 2 + 0], -2.f, zr[mi][rh] + ev[ni][0]));
                    v = fminf(v, __fmaf_rn(c[mi][ni][rh * 2 + 1], -2.f, zr[mi][rh] + ev[ni][1]));
                }
                v = fminf(v, __shfl_xor_sync(0xffffffffu, v, 1));
                v = fminf(v, __shfl_xor_sync(0xffffffffu, v, 2));
                if (q == 0)
                    red[wn * 128 + wm * 64 + mi * 16 + rh * 8 + g] = v;
            }
        }
        __syncthreads();
        if (tid < 128) {
            float h0 = fminf(red[tid],       red[128 + tid]);   // codes 0..63
            float h1 = fminf(red[256 + tid], red[384 + tid]);   // codes 64..127
            g_tmin[(size_t)(j * 2 + 0) * N_ROWS + rowbase + tid] = h0;
            g_tmin[(size_t)(j * 2 + 1) * N_ROWS + rowbase + tid] = h1;
        }
        __syncthreads();
    }
}

// ---------------------------------------------------------------------------
// Kernel 3: per-row exact rescore of candidate tiles; emits index, z_q, loss.
// ---------------------------------------------------------------------------
__global__ void __launch_bounds__(128) rescore_kernel(const float* __restrict__ z,
                                                      const float* __restrict__ emb,
                                                      float* __restrict__ out)
{
    __shared__ float  zs[DIM];
    __shared__ float  smin[128];
    __shared__ int    list[NT64];
    __shared__ int    cnt;
    __shared__ float  stage[64 * 145];    // padded stride 145: bank-safe
    __shared__ float  rbv[128];
    __shared__ int    rbi[128];
    __shared__ double dred[128];

    const int row = blockIdx.x;
    const int tid = threadIdx.x;

    // pass over tile mins: cache locally, find global min
    float tv[7]; int ti[7]; int nl = 0;
    float m = CUDART_INF_F;
    for (int i = tid; i < NT64; i += 128) {
        float v = g_tmin[(size_t)i * N_ROWS + row];
        tv[nl] = v; ti[nl] = i; ++nl;
        m = fminf(m, v);
    }
    for (int i = tid; i < DIM; i += 128) zs[i] = z[(size_t)row * DIM + i];
    if (tid == 0) cnt = 0;
    smin[tid] = m;
    __syncthreads();
    for (int s = 64; s > 0; s >>= 1) {
        if (tid < s) smin[tid] = fminf(smin[tid], smin[tid + s]);
        __syncthreads();
    }
    const float tau = smin[0] + MARGIN;
    for (int u = 0; u < nl; ++u)
        if (tv[u] <= tau) list[atomicAdd(&cnt, 1)] = ti[u];
    __syncthreads();
    const int nc = cnt;
    const float zn = g_zn[row];

    float bv = CUDART_INF_F;
    int   bi = 0x7fffffff;
    for (int li = 0; li < nc; ++li) {
        const int t64 = list[li];
        const int cb = t64 * 64;
        for (int idx = tid; idx < 64 * DIM; idx += 128) {
            int r = idx / DIM;
            int col = idx - r * DIM;
            int code = cb + r;
            stage[r * 145 + col] = (code < KCODES) ? emb[(size_t)code * DIM + col] : 0.f;
        }
        __syncthreads();
        if (tid < 64) {
            int code = cb + tid;
            if (code < KCODES) {
                float acc = 0.f;
                const float* es = &stage[tid * 145];
                #pragma unroll 8
                for (int d = 0; d < DIM; ++d)
                    acc = __fmaf_rn(zs[d], es[d], acc);
                float t1 = __fadd_rn(zn, g_en[code]);
                float dd = __fmaf_rn(acc, -2.f, t1);
                if (dd < bv || (dd == bv && code < bi)) { bv = dd; bi = code; }
            }
        }
        __syncthreads();
    }

    rbv[tid] = bv; rbi[tid] = bi;
    __syncthreads();
    for (int s = 64; s > 0; s >>= 1) {
        if (tid < s) {
            float v2 = rbv[tid + s]; int b2 = rbi[tid + s];
            if (v2 < rbv[tid] || (v2 == rbv[tid] && b2 < rbi[tid])) {
                rbv[tid] = v2; rbi[tid] = b2;
            }
        }
        __syncthreads();
    }
    const int wbi = rbi[0];
    if (tid == 0) out[ZQ_ELEMS + row] = (float)wbi;

    double ls = 0.0;
    for (int i = tid; i < DIM; i += 128) {
        float e = emb[(size_t)wbi * DIM + i];
        out[(size_t)row * DIM + i] = e;
        float dx = e - zs[i];
        ls += (double)dx * dx;
    }
    dred[tid] = ls;
    __syncthreads();
    for (int s = 64; s > 0; s >>= 1) {
        if (tid < s) dred[tid] += dred[tid + s];
        __syncthreads();
    }
    if (tid == 0) g_rowloss[row] = dred[0];
}

// Kernel 4: deterministic loss reduction.
__global__ void loss_kernel(float* __restrict__ out)
{
    __shared__ double dred[256];
    int tid = threadIdx.x;
    double s = 0.0;
    for (int i = tid; i < N_ROWS; i += 256) s += g_rowloss[i];
    dred[tid] = s;
    __syncthreads();
    for (int st = 128; st > 0; st >>= 1) {
        if (tid < st) dred[tid] += dred[tid + st];
        __syncthreads();
    }
    if (tid == 0) out[ZQ_ELEMS + N_ROWS] = (float)(dred[0] / (double)ZQ_ELEMS);
}

// ---------------------------------------------------------------------------
extern "C" void kernel_launch(void* const* d_in, const int* in_sizes, int n_in,
                              void* d_out, int out_size)
{
    const float* z = nullptr;
    const float* emb = nullptr;
    for (int i = 0; i < n_in; ++i) {
        if (in_sizes[i] == N_ROWS * DIM)      z = (const float*)d_in[i];
        else if (in_sizes[i] == KCODES * DIM) emb = (const float*)d_in[i];
    }
    float* out = (float*)d_out;
    (void)out_size;

    cudaFuncSetAttribute(gemm_kernel,
                         cudaFuncAttributeMaxDynamicSharedMemorySize, GEMM_SMEM);

    prep_kernel<<<(KPADC + 255) / 256, 256>>>(z, emb);
    gemm_kernel<<<dim3(N_ROWS / 128, NCHUNK), 256, GEMM_SMEM>>>();
    rescore_kernel<<<N_ROWS, 128>>>(z, emb, out);
    loss_kernel<<<1, 256>>>(out);
}